// round 13
// baseline (speedup 1.0000x reference)
#include <cuda_runtime.h>
#include <math.h>

// Photonic mesh simulator, N=128. R13 = R12 minus register spills.
// R12 hit regs=254 (ceiling) -> ring spilled to local mem (L1 22.9%, L2 18.4%),
// 188 cyc/layer vs ~45 issue. Fixes: RING 8->4 (frees 32 regs), rotation via
// one 64-bit XOR (-s from s; ALU pipe) saving 1 FMA-pipe op/group/layer,
// pointer-increment table walk.
//
// Layout: sync-free warp-per-column; thread t owns pairs 4t..4t+3 packed as
// f32x2 groups (g=0: pairs 0,1; g=1: pairs 2,3; lo/hi lanes). Deferred-scale
// normalized algebra: MMI = PM*[[1,ir],[ir,1]], CROSS = QX*[[r2,i],[i,r2]],
// endpoints identity; exact rescale RS16 = PM^16*QX^8 every 16 layers; tail
// scale folded into MMI_OUT.

#define N_ 128
#define NLAYERS 255   // 2N-1
#define RING 4

typedef unsigned long long u64;

// float4 per (layer, mode-pair u): (c(2u), c(2u+1), s(2u), s(2u+1))
// + RING+2 padded layers so the ring prefetch never goes OOB
__device__ __align__(16) float4 g_tab[(NLAYERS + RING + 2) * (N_ / 2)];

__global__ void precompute_cs_kernel(const float* __restrict__ theta_even) {
    const int L = blockIdx.x;        // layer
    const int u = threadIdx.x;       // mode-pair 0..63
    if (L < NLAYERS) {
        float s0, c0, s1, c1;
        sincosf(theta_even[L * N_ + 2 * u], &s0, &c0);
        sincosf(theta_even[L * N_ + 2 * u + 1], &s1, &c1);
        g_tab[L * 64 + u] = make_float4(c0, c1, s0, s1);
    } else {
        g_tab[L * 64 + u] = make_float4(1.f, 1.f, 0.f, 0.f);
    }
}

// ---- packed f32x2 helpers ----
__device__ __forceinline__ u64 pk2(float lo, float hi) {
    u64 r; asm("mov.b64 %0, {%1,%2};" : "=l"(r) : "f"(lo), "f"(hi)); return r;
}
__device__ __forceinline__ u64 fma2(u64 a, u64 b, u64 c) {
    u64 d; asm("fma.rn.f32x2 %0, %1, %2, %3;" : "=l"(d) : "l"(a), "l"(b), "l"(c)); return d;
}
__device__ __forceinline__ u64 mul2(u64 a, u64 b) {
    u64 d; asm("mul.rn.f32x2 %0, %1, %2;" : "=l"(d) : "l"(a), "l"(b)); return d;
}
#define NEG2(v) ((v) ^ 0x8000000080000000ULL)

union R2u { u64 v; float f[2]; };
union F4U { float4 v; u64 p[2]; };   // p[0]=(c_lo,c_hi), p[1]=(s_lo,s_hi)

__global__ void __launch_bounds__(32, 1) mesh_kernel(
    const float* __restrict__ theta_in,
    const float* __restrict__ theta_out,
    float* __restrict__ out,
    float PMc, float QMc,     // true MMI coeffs (init only)
    float rC,                 // QM/PM
    float r2C,                // PX/QX
    float RS16c,              // PM^16 * QX^8
    float PMfc, float QMfc)   // PM,QM folded with tail scale PM^14*QX^7
{
    const int t   = threadIdx.x;     // 0..31
    const int col = blockIdx.x;      // column
    const int pbase = 4 * t;         // first owned pair

    const u64 RC2  = pk2(rC, rC);
    const u64 NR2  = pk2(-rC, -rC);
    const u64 RS2  = pk2(RS16c, RS16c);
    const float r2 = r2C;

    // packed state: group0: pairs pbase+0 (lo), pbase+1 (hi);
    //               group1: pairs pbase+2 (lo), pbase+3 (hi)
    R2u Ar[2], Ai[2], Br[2], Bi[2];
    #pragma unroll
    for (int g = 0; g < 2; ++g) { Ar[g].v = 0; Ai[g].v = 0; Br[g].v = 0; Bi[g].v = 0; }

    // init: MMI_IN @ diag(e^{i th_in}); column col excites pair index col
    if (col >= pbase && col < pbase + 4) {
        float si, ci;
        sincosf(theta_in[col], &si, &ci);
        int i = col - pbase;          // 0..3
        int g = i >> 1, l = i & 1;
        Ar[g].f[l] = PMc * ci;  Ai[g].f[l] = PMc * si;
        Br[g].f[l] = -QMc * si; Bi[g].f[l] = QMc * ci;
    }

    // ring: slot j holds the 2 table float4 of layer k (k%4==j)
    const float4* tab = g_tab + 2 * t;   // layer stride = 64 float4
    F4U q[RING][2];
    #pragma unroll
    for (int j = 0; j < RING; ++j) {
        q[j][0].v = tab[j * 64];
        q[j][1].v = tab[j * 64 + 1];
    }
    const float4* pre = tab + RING * 64;   // -> layer k+RING, advanced per layer

    // normalized layer on group g: phase rotation (4 FMA + 1 XOR) + mix (4 FMA)
    auto layerg = [&](int g, const F4U& f) {
        u64 c2 = f.p[0], s2 = f.p[1], ns2 = NEG2(s2);
        u64 ur = fma2(Ai[g].v, ns2, mul2(Ar[g].v, c2));   // a_r*c - a_i*s
        u64 ui = fma2(Ai[g].v, c2,  mul2(Ar[g].v, s2));   // a_r*s + a_i*c
        u64 n0r = fma2(NR2, Bi[g].v, ur);                 // u - r*b_i (re)
        u64 n0i = fma2(RC2, Br[g].v, ui);
        u64 n1r = fma2(NR2, ui, Br[g].v);                 // b - r*u_i (re)
        u64 n1i = fma2(RC2, ur, Bi[g].v);
        Ar[g].v = n0r; Ai[g].v = n0i; Br[g].v = n1r; Bi[g].v = n1i;
    };

    // normalized cross: each element: r2*self + i*partner; endpoints identity
    auto cross = [&]() {
        float pb3r = __shfl_up_sync(0xffffffffu, Br[1].f[1], 1);
        float pb3i = __shfl_up_sync(0xffffffffu, Bi[1].f[1], 1);
        float xna0r = __shfl_down_sync(0xffffffffu, Ar[0].f[0], 1);
        float xna0i = __shfl_down_sync(0xffffffffu, Ai[0].f[0], 1);

        float a0r = Ar[0].f[0], a0i = Ai[0].f[0];
        float a1r = Ar[0].f[1], a1i = Ai[0].f[1];
        float a2r = Ar[1].f[0], a2i = Ai[1].f[0];
        float a3r = Ar[1].f[1], a3i = Ai[1].f[1];
        float b0r = Br[0].f[0], b0i = Bi[0].f[0];
        float b1r = Br[0].f[1], b1i = Bi[0].f[1];
        float b2r = Br[1].f[0], b2i = Bi[1].f[0];
        float b3r = Br[1].f[1], b3i = Bi[1].f[1];

        float ya0r = (t == 0) ? a0r : fmaf(r2, a0r, -pb3i);
        float ya0i = (t == 0) ? a0i : fmaf(r2, a0i,  pb3r);
        float ya1r = fmaf(r2, a1r, -b0i), ya1i = fmaf(r2, a1i, b0r);
        float ya2r = fmaf(r2, a2r, -b1i), ya2i = fmaf(r2, a2i, b1r);
        float ya3r = fmaf(r2, a3r, -b2i), ya3i = fmaf(r2, a3i, b2r);
        float yb0r = fmaf(r2, b0r, -a1i), yb0i = fmaf(r2, b0i, a1r);
        float yb1r = fmaf(r2, b1r, -a2i), yb1i = fmaf(r2, b1i, a2r);
        float yb2r = fmaf(r2, b2r, -a3i), yb2i = fmaf(r2, b2i, a3r);
        float yb3r = (t == 31) ? b3r : fmaf(r2, b3r, -xna0i);
        float yb3i = (t == 31) ? b3i : fmaf(r2, b3i,  xna0r);

        Ar[0].f[0] = ya0r; Ai[0].f[0] = ya0i;
        Ar[0].f[1] = ya1r; Ai[0].f[1] = ya1i;
        Ar[1].f[0] = ya2r; Ai[1].f[0] = ya2i;
        Ar[1].f[1] = ya3r; Ai[1].f[1] = ya3i;
        Br[0].f[0] = yb0r; Bi[0].f[0] = yb0i;
        Br[0].f[1] = yb1r; Bi[0].f[1] = yb1i;
        Br[1].f[0] = yb2r; Bi[1].f[0] = yb2i;
        Br[1].f[1] = yb3r; Bi[1].f[1] = yb3i;
    };

    // mainloop: 15 groups x 16 layers (0..239); exact rescale RS16 per group
    for (int g = 0; g < 15; ++g) {
        #pragma unroll
        for (int j = 0; j < 16; ++j) {
            const int sl = j & (RING - 1);
            F4U f0 = q[sl][0], f1 = q[sl][1];
            q[sl][0].v = pre[0];                  // prefetch layer k+4
            q[sl][1].v = pre[1];
            pre += 64;
            layerg(0, f0);
            layerg(1, f1);
            if ((j & 1) == 0) cross();            // k even <=> j even
        }
        #pragma unroll
        for (int gg = 0; gg < 2; ++gg) {          // exact rescale
            Ar[gg].v = mul2(Ar[gg].v, RS2);
            Ai[gg].v = mul2(Ai[gg].v, RS2);
            Br[gg].v = mul2(Br[gg].v, RS2);
            Bi[gg].v = mul2(Bi[gg].v, RS2);
        }
    }
    // tail: layers 240..253 (7 crosses); scale folded into PMf/QMf below
    #pragma unroll
    for (int j = 0; j < 14; ++j) {
        const int sl = j & (RING - 1);
        F4U f0 = q[sl][0], f1 = q[sl][1];
        q[sl][0].v = pre[0];
        q[sl][1].v = pre[1];
        pre += 64;
        layerg(0, f0);
        layerg(1, f1);
        if ((j & 1) == 0) cross();
    }

    // Phase(254) only: slot 254&3 = 2 (loaded while processing layer 250)
    #pragma unroll
    for (int g = 0; g < 2; ++g) {
        u64 c2 = q[2][g].p[0], s2 = q[2][g].p[1], ns2 = NEG2(s2);
        u64 ur = fma2(Ai[g].v, ns2, mul2(Ar[g].v, c2));
        u64 ui = fma2(Ai[g].v, c2,  mul2(Ar[g].v, s2));
        Ar[g].v = ur; Ai[g].v = ui;
    }

    // MMI_OUT (with folded tail scale) + output phase; output = real part
    #pragma unroll
    for (int i = 0; i < 4; ++i) {
        const int g = i >> 1, l = i & 1;
        const int m = pbase + i;
        float orr = fmaf(PMfc, Ar[g].f[l], -QMfc * Bi[g].f[l]);
        float oii = fmaf(PMfc, Ai[g].f[l],  QMfc * Br[g].f[l]);
        float so, co;
        sincosf(theta_out[m], &so, &co);
        out[m * N_ + col] = fmaf(orr, co, -oii * so);
    }
}

extern "C" void kernel_launch(void* const* d_in, const int* in_sizes, int n_in,
                              void* d_out, int out_size) {
    // theta_even is the (2N-1)*N array; theta_in first N-sized, theta_out second.
    const float* theta_even = nullptr;
    const float* smalls[2] = {nullptr, nullptr};
    int ns = 0;
    for (int i = 0; i < n_in; ++i) {
        if (in_sizes[i] == NLAYERS * N_) {
            theta_even = (const float*)d_in[i];
        } else if (ns < 2) {
            smalls[ns++] = (const float*)d_in[i];
        }
    }
    const float* theta_in  = smalls[0];
    const float* theta_out = smalls[1];

    // exact constants in double, rounded once to float
    const double aM = sqrt(1.0 - 0.05), p = sqrt(0.505), q = sqrt(0.495);
    const double PM = aM * p, QM = aM * q, r = q / p;
    const double aX = sqrt(1.0 - 0.02);
    const double QX = aX * sqrt(0.99);
    const double r2 = sqrt(0.01 / 0.99);
    const double RS16 = pow(PM, 16) * pow(QX, 8);
    const double RSrem = pow(PM, 14) * pow(QX, 7);

    precompute_cs_kernel<<<(NLAYERS + RING + 2), 64>>>(theta_even);
    mesh_kernel<<<N_, 32>>>(theta_in, theta_out, (float*)d_out,
                            (float)PM, (float)QM, (float)r, (float)r2,
                            (float)RS16, (float)(PM * RSrem), (float)(QM * RSrem));
}

// round 14
// speedup vs baseline: 1.2995x; 1.2995x over previous
#include <cuda_runtime.h>
#include <math.h>

// Photonic mesh simulator, N=128. R14 = R12/R13 algebra with a register-clean
// implementation. R12/R13 used arrays-of-unions with one RUNTIME-indexed
// access (init: Ar[g].f[l]) -> ptxas demoted all state to LOCAL MEMORY
// (L1 ~20%, regs ~222, issue 94% of 1-warp ceiling = mostly LDL/STL).
// Fix: 8 named u64 state registers, compile-time-only indexing, no unions;
// lane access via mov.b64 asm; ring as ulonglong2 with constant indices.
//
// Algebra (validated in R12, rel_err 1.1e-5): normalized MMI = [[1,ir],[ir,1]]
// (r=QM/PM), normalized CROSS = [[r2,i],[i,r2]] (r2=PX/QX; endpoints identity
// since CE==QX); exact rescale RS16 = PM^16*QX^8 every 16 layers; tail scale
// PM^14*QX^7 folded into MMI_OUT. f32x2-packed: pairs (lo,hi) per group.

#define N_ 128
#define NLAYERS 255   // 2N-1
#define RING 4

typedef unsigned long long u64;

// float4 per (layer, mode-pair u): (c(2u), c(2u+1), s(2u), s(2u+1))
__device__ __align__(16) float4 g_tab[(NLAYERS + RING + 2) * (N_ / 2)];

__global__ void precompute_cs_kernel(const float* __restrict__ theta_even) {
    const int L = blockIdx.x;        // layer
    const int u = threadIdx.x;       // mode-pair 0..63
    if (L < NLAYERS) {
        float s0, c0, s1, c1;
        sincosf(theta_even[L * N_ + 2 * u], &s0, &c0);
        sincosf(theta_even[L * N_ + 2 * u + 1], &s1, &c1);
        g_tab[L * 64 + u] = make_float4(c0, c1, s0, s1);
    } else {
        g_tab[L * 64 + u] = make_float4(1.f, 1.f, 0.f, 0.f);
    }
}

// ---- packed f32x2 helpers (no unions; register-view movs) ----
__device__ __forceinline__ u64 pk2(float lo, float hi) {
    u64 r; asm("mov.b64 %0, {%1,%2};" : "=l"(r) : "f"(lo), "f"(hi)); return r;
}
__device__ __forceinline__ void upk2(u64 v, float& lo, float& hi) {
    asm("mov.b64 {%0,%1}, %2;" : "=f"(lo), "=f"(hi) : "l"(v));
}
__device__ __forceinline__ u64 fma2(u64 a, u64 b, u64 c) {
    u64 d; asm("fma.rn.f32x2 %0, %1, %2, %3;" : "=l"(d) : "l"(a), "l"(b), "l"(c)); return d;
}
__device__ __forceinline__ u64 mul2(u64 a, u64 b) {
    u64 d; asm("mul.rn.f32x2 %0, %1, %2;" : "=l"(d) : "l"(a), "l"(b)); return d;
}
#define NEG2(v) ((v) ^ 0x8000000080000000ULL)

__global__ void __launch_bounds__(32, 1) mesh_kernel(
    const float* __restrict__ theta_in,
    const float* __restrict__ theta_out,
    float* __restrict__ out,
    float PMc, float QMc,     // true MMI coeffs (init only)
    float rC,                 // QM/PM
    float r2C,                // PX/QX
    float RS16c,              // PM^16 * QX^8
    float PMfc, float QMfc)   // PM,QM folded with tail scale PM^14*QX^7
{
    const int t   = threadIdx.x;     // 0..31
    const int col = blockIdx.x;      // column
    const int pbase = 4 * t;         // first owned pair

    const u64 RC2 = pk2(rC, rC);
    const u64 NR2 = pk2(-rC, -rC);
    const u64 RS2 = pk2(RS16c, RS16c);
    const float r2 = r2C;

    // ---- named packed state (group0: pairs pbase+0 lo / pbase+1 hi;
    //                          group1: pairs pbase+2 lo / pbase+3 hi) ----
    u64 Ar0, Ai0, Br0, Bi0, Ar1, Ai1, Br1, Bi1;

    // init: MMI_IN @ diag(e^{i th_in}); column col excites pair index col.
    // Compile-time structure only: per-lane selects, no runtime array indexing.
    {
        float si, ci;
        sincosf(theta_in[col], &si, &ci);
        const float er = PMc * ci,  ei = PMc * si;
        const float fr = -QMc * si, fi = QMc * ci;
        const bool e0 = (pbase + 0 == col), e1 = (pbase + 1 == col);
        const bool e2 = (pbase + 2 == col), e3 = (pbase + 3 == col);
        Ar0 = pk2(e0 ? er : 0.f, e1 ? er : 0.f);
        Ai0 = pk2(e0 ? ei : 0.f, e1 ? ei : 0.f);
        Br0 = pk2(e0 ? fr : 0.f, e1 ? fr : 0.f);
        Bi0 = pk2(e0 ? fi : 0.f, e1 ? fi : 0.f);
        Ar1 = pk2(e2 ? er : 0.f, e3 ? er : 0.f);
        Ai1 = pk2(e2 ? ei : 0.f, e3 ? ei : 0.f);
        Br1 = pk2(e2 ? fr : 0.f, e3 ? fr : 0.f);
        Bi1 = pk2(e2 ? fi : 0.f, e3 ? fi : 0.f);
    }

    // ring: slot j holds layer k (k%4==j); entry .x=(c_lo,c_hi), .y=(s_lo,s_hi)
    const ulonglong2* tab = reinterpret_cast<const ulonglong2*>(g_tab) + 2 * t;
    ulonglong2 q[RING][2];
    #pragma unroll
    for (int j = 0; j < RING; ++j) {
        q[j][0] = tab[j * 64];
        q[j][1] = tab[j * 64 + 1];
    }
    const ulonglong2* pre = tab + RING * 64;   // layer k+RING, advanced per layer

    // normalized layer on group 0
    auto layer0 = [&](ulonglong2 f) {
        u64 c2 = f.x, s2 = f.y, ns2 = NEG2(s2);
        u64 ur = fma2(Ai0, ns2, mul2(Ar0, c2));
        u64 ui = fma2(Ai0, c2,  mul2(Ar0, s2));
        u64 n0r = fma2(NR2, Bi0, ur);
        u64 n0i = fma2(RC2, Br0, ui);
        u64 n1r = fma2(NR2, ui, Br0);
        u64 n1i = fma2(RC2, ur, Bi0);
        Ar0 = n0r; Ai0 = n0i; Br0 = n1r; Bi0 = n1i;
    };
    auto layer1 = [&](ulonglong2 f) {
        u64 c2 = f.x, s2 = f.y, ns2 = NEG2(s2);
        u64 ur = fma2(Ai1, ns2, mul2(Ar1, c2));
        u64 ui = fma2(Ai1, c2,  mul2(Ar1, s2));
        u64 n0r = fma2(NR2, Bi1, ur);
        u64 n0i = fma2(RC2, Br1, ui);
        u64 n1r = fma2(NR2, ui, Br1);
        u64 n1i = fma2(RC2, ur, Bi1);
        Ar1 = n0r; Ai1 = n0i; Br1 = n1r; Bi1 = n1i;
    };

    // normalized cross: y = r2*self + i*partner; endpoints identity
    auto cross = [&]() {
        float a0r, a1r, a0i, a1i, a2r, a3r, a2i, a3i;
        float b0r, b1r, b0i, b1i, b2r, b3r, b2i, b3i;
        upk2(Ar0, a0r, a1r); upk2(Ai0, a0i, a1i);
        upk2(Ar1, a2r, a3r); upk2(Ai1, a2i, a3i);
        upk2(Br0, b0r, b1r); upk2(Bi0, b0i, b1i);
        upk2(Br1, b2r, b3r); upk2(Bi1, b2i, b3i);

        float pb3r = __shfl_up_sync(0xffffffffu, b3r, 1);
        float pb3i = __shfl_up_sync(0xffffffffu, b3i, 1);
        float xna0r = __shfl_down_sync(0xffffffffu, a0r, 1);
        float xna0i = __shfl_down_sync(0xffffffffu, a0i, 1);

        float ya0r = (t == 0) ? a0r : fmaf(r2, a0r, -pb3i);
        float ya0i = (t == 0) ? a0i : fmaf(r2, a0i,  pb3r);
        float ya1r = fmaf(r2, a1r, -b0i), ya1i = fmaf(r2, a1i, b0r);
        float ya2r = fmaf(r2, a2r, -b1i), ya2i = fmaf(r2, a2i, b1r);
        float ya3r = fmaf(r2, a3r, -b2i), ya3i = fmaf(r2, a3i, b2r);
        float yb0r = fmaf(r2, b0r, -a1i), yb0i = fmaf(r2, b0i, a1r);
        float yb1r = fmaf(r2, b1r, -a2i), yb1i = fmaf(r2, b1i, a2r);
        float yb2r = fmaf(r2, b2r, -a3i), yb2i = fmaf(r2, b2i, a3r);
        float yb3r = (t == 31) ? b3r : fmaf(r2, b3r, -xna0i);
        float yb3i = (t == 31) ? b3i : fmaf(r2, b3i,  xna0r);

        Ar0 = pk2(ya0r, ya1r); Ai0 = pk2(ya0i, ya1i);
        Ar1 = pk2(ya2r, ya3r); Ai1 = pk2(ya2i, ya3i);
        Br0 = pk2(yb0r, yb1r); Bi0 = pk2(yb0i, yb1i);
        Br1 = pk2(yb2r, yb3r); Bi1 = pk2(yb2i, yb3i);
    };

    // mainloop: 15 groups x 16 layers (0..239); exact rescale RS16 per group
    for (int g = 0; g < 15; ++g) {
        #pragma unroll
        for (int j = 0; j < 16; ++j) {
            const int sl = j & (RING - 1);
            ulonglong2 f0 = q[sl][0], f1 = q[sl][1];
            q[sl][0] = pre[0];                    // prefetch layer k+4
            q[sl][1] = pre[1];
            pre += 64;
            layer0(f0);
            layer1(f1);
            if ((j & 1) == 0) cross();            // k even <=> j even
        }
        Ar0 = mul2(Ar0, RS2); Ai0 = mul2(Ai0, RS2);
        Br0 = mul2(Br0, RS2); Bi0 = mul2(Bi0, RS2);
        Ar1 = mul2(Ar1, RS2); Ai1 = mul2(Ai1, RS2);
        Br1 = mul2(Br1, RS2); Bi1 = mul2(Bi1, RS2);
    }
    // tail: layers 240..253 (7 crosses); scale folded into PMf/QMf below
    #pragma unroll
    for (int j = 0; j < 14; ++j) {
        const int sl = j & (RING - 1);
        ulonglong2 f0 = q[sl][0], f1 = q[sl][1];
        q[sl][0] = pre[0];
        q[sl][1] = pre[1];
        pre += 64;
        layer0(f0);
        layer1(f1);
        if ((j & 1) == 0) cross();
    }

    // Phase(254) only: slot 254&3 = 2
    {
        u64 c2 = q[2][0].x, s2 = q[2][0].y, ns2 = NEG2(s2);
        u64 ur = fma2(Ai0, ns2, mul2(Ar0, c2));
        u64 ui = fma2(Ai0, c2,  mul2(Ar0, s2));
        Ar0 = ur; Ai0 = ui;
        u64 d2 = q[2][1].x, e2 = q[2][1].y, ne2 = NEG2(e2);
        u64 vr = fma2(Ai1, ne2, mul2(Ar1, d2));
        u64 vi = fma2(Ai1, d2,  mul2(Ar1, e2));
        Ar1 = vr; Ai1 = vi;
    }

    // MMI_OUT (with folded tail scale) + output phase; output = real part
    {
        float a0r, a1r, a0i, a1i, a2r, a3r, a2i, a3i;
        float b0r, b1r, b0i, b1i, b2r, b3r, b2i, b3i;
        upk2(Ar0, a0r, a1r); upk2(Ai0, a0i, a1i);
        upk2(Ar1, a2r, a3r); upk2(Ai1, a2i, a3i);
        upk2(Br0, b0r, b1r); upk2(Bi0, b0i, b1i);
        upk2(Br1, b2r, b3r); upk2(Bi1, b2i, b3i);

        float so, co;
        float orr, oii;

        orr = fmaf(PMfc, a0r, -QMfc * b0i);
        oii = fmaf(PMfc, a0i,  QMfc * b0r);
        sincosf(theta_out[pbase + 0], &so, &co);
        out[(pbase + 0) * N_ + col] = fmaf(orr, co, -oii * so);

        orr = fmaf(PMfc, a1r, -QMfc * b1i);
        oii = fmaf(PMfc, a1i,  QMfc * b1r);
        sincosf(theta_out[pbase + 1], &so, &co);
        out[(pbase + 1) * N_ + col] = fmaf(orr, co, -oii * so);

        orr = fmaf(PMfc, a2r, -QMfc * b2i);
        oii = fmaf(PMfc, a2i,  QMfc * b2r);
        sincosf(theta_out[pbase + 2], &so, &co);
        out[(pbase + 2) * N_ + col] = fmaf(orr, co, -oii * so);

        orr = fmaf(PMfc, a3r, -QMfc * b3i);
        oii = fmaf(PMfc, a3i,  QMfc * b3r);
        sincosf(theta_out[pbase + 3], &so, &co);
        out[(pbase + 3) * N_ + col] = fmaf(orr, co, -oii * so);
    }
}

extern "C" void kernel_launch(void* const* d_in, const int* in_sizes, int n_in,
                              void* d_out, int out_size) {
    // theta_even is the (2N-1)*N array; theta_in first N-sized, theta_out second.
    const float* theta_even = nullptr;
    const float* smalls[2] = {nullptr, nullptr};
    int ns = 0;
    for (int i = 0; i < n_in; ++i) {
        if (in_sizes[i] == NLAYERS * N_) {
            theta_even = (const float*)d_in[i];
        } else if (ns < 2) {
            smalls[ns++] = (const float*)d_in[i];
        }
    }
    const float* theta_in  = smalls[0];
    const float* theta_out = smalls[1];

    // exact constants in double, rounded once to float
    const double aM = sqrt(1.0 - 0.05), p = sqrt(0.505), q = sqrt(0.495);
    const double PM = aM * p, QM = aM * q, r = q / p;
    const double aX = sqrt(1.0 - 0.02);
    const double QX = aX * sqrt(0.99);
    const double r2 = sqrt(0.01 / 0.99);
    const double RS16 = pow(PM, 16) * pow(QX, 8);
    const double RSrem = pow(PM, 14) * pow(QX, 7);

    precompute_cs_kernel<<<(NLAYERS + RING + 2), 64>>>(theta_even);
    mesh_kernel<<<N_, 32>>>(theta_in, theta_out, (float*)d_out,
                            (float)PM, (float)QM, (float)r, (float)r2,
                            (float)RS16, (float)(PM * RSrem), (float)(QM * RSrem));
}